// round 10
// baseline (speedup 1.0000x reference)
#include <cuda_runtime.h>

// EKVNonLinearConv, u-space table + warp-uniform skip, 2 output rows per thread,
// ci-split shared tile for high occupancy.
//   f(d) = sp(min(a,20))^2 - sp(min(a-D,20))^2, a=d/0.075, D=0.1/0.075
//   u = saturate(vg*INVR + ub), ub = (0.96 - clip(th,1,8))/2.58
//   idx = floor(u*516); tab entries >= 512 exact zero (d >= 1.6).
//   Kinks d=1.5 -> 492, d=1.6 -> 512 (on-grid). out = ALPHA*R*scale * sum_l f.

#define CIN    16
#define CIH    8              // ci per half-pass
#define COUTT  64
#define HH     32
#define WW     32
#define BB     8
#define PR     2              // output rows per thread
#define NWARP  8
#define NTHR   256
#define RPB    (NWARP * PR)   // 16 output rows per block
#define TILR   (RPB + 2)      // 18 tile rows incl halo
#define LPC    144

#define TABN   516
#define TABEXT 518
#define TD0    (-0.96f)
#define THD    0.005f
#define INVR   0.3875968992248062f   // 1/2.58
#define USCALE 516.0f

__device__ float2 g_tab[TABEXT]; // (a0, a1): f ~= a1*u + a0 on interval i

__device__ __forceinline__ float ekv_exact(float d) {
    const float INVD  = 13.333333333333334f;
    const float DELTA = 1.3333333333333333f;
    float a  = d * INVD;
    float a1 = fminf(fmaxf(a, -50.0f), 20.0f);
    float a2 = fminf(fmaxf(a - DELTA, -50.0f), 20.0f);
    float l1 = log1pf(expf(a1));
    float l2 = log1pf(expf(a2));
    return fmaf(l1, l1, -l2 * l2);
}

__global__ void build_table_kernel() {
    int i = blockIdx.x * blockDim.x + threadIdx.x;
    if (i < TABEXT) {
        float f0 = ekv_exact(TD0 + (float)i * THD);
        float f1 = ekv_exact(TD0 + (float)(i + 1) * THD);
        float a1 = (f1 - f0) * USCALE;           // slope per unit u
        float u0 = (float)i * (1.0f / USCALE);
        g_tab[i] = make_float2(fmaf(-a1, u0, f0), a1);   // i>=512: exact (0,0)
    }
}

__global__ __launch_bounds__(NTHR)
void ekv_conv_kernel(const float* __restrict__ x,
                     const float* __restrict__ theta,
                     const float* __restrict__ scale,
                     float* __restrict__ out)
{
    __shared__ float  sx[CIH][TILR][34];     // half-tile (19.1 KB)
    __shared__ float4 swb[CIN * 3];          // ub per (ci*3+ky), kx triple (768 B)
    __shared__ float  sthr[CIH][TILR];       // (0.11 - rowmax)*INVR
    __shared__ float2 tab[TABEXT];           // ~4 KB

    const int rt = blockIdx.x;       // row tile 0..1
    const int co = blockIdx.y;       // cout 0..63
    const int b  = blockIdx.z;       // batch
    const int y0 = rt * RPB;
    const int tid = threadIdx.x;

    // ---- copy table from global (L2-hot) ----
    {
        const float4* src = (const float4*)g_tab;
        float4*       dst = (float4*)tab;
        for (int i = tid; i < TABEXT / 2; i += NTHR) dst[i] = src[i];
    }
    // ---- theta -> ub = (0.96 - clip(th)) / 2.58, packed per kx-triple ----
    for (int i = tid; i < CIN * 3; i += NTHR) {
        const float* tp = theta + co * LPC + i * 3;
        float t0 = fminf(fmaxf(tp[0], 1.0f), 8.0f);
        float t1 = fminf(fmaxf(tp[1], 1.0f), 8.0f);
        float t2 = fminf(fmaxf(tp[2], 1.0f), 8.0f);
        swb[i] = make_float4((0.96f - t0) * INVR,
                             (0.96f - t1) * INVR,
                             (0.96f - t2) * INVR, 0.0f);
    }

    const int tx  = tid & 31;    // output column
    const int wid = tid >> 5;    // warp id 0..7; handles rows y0+2*wid, +1

    float accA = 0.0f, accB = 0.0f;

#define EKV_TERM(VG, UB, ACC) do {                                   \
        float u_ = __saturatef(fmaf((VG), INVR, (UB)));              \
        int idx_ = __float2int_rd(u_ * USCALE);                      \
        float2 e_ = tab[idx_];                                       \
        (ACC) += fmaf(e_.y, u_, e_.x);                               \
    } while (0)

    #pragma unroll 1
    for (int half = 0; half < 2; half++) {
        const int ci0 = half * CIH;
        __syncthreads();   // all warps done with previous half's tile

        // ---- load x half-tile (zero-padded) ----
        for (int i = tid; i < CIH * TILR * 34; i += NTHR) {
            int cc = i % 34;
            int r  = (i / 34) % TILR;
            int ci = i / (34 * TILR);
            int gy = y0 - 1 + r;
            int gx = cc - 1;
            float v = 0.0f;
            if (gy >= 0 && gy < HH && gx >= 0 && gx < WW)
                v = x[((b * CIN + ci0 + ci) * HH + gy) * WW + gx];
            sx[ci][r][cc] = v;
        }
        __syncthreads();

        // ---- per-(ci,row) skip threshold: term active iff ub > sthr ----
        for (int i = tid; i < CIH * TILR; i += NTHR) {
            int r  = i % TILR;
            int ci = i / TILR;
            float m = -1e30f;
            #pragma unroll
            for (int cc = 0; cc < 34; cc++) m = fmaxf(m, sx[ci][r][cc]);
            sthr[ci][r] = (0.11f - m) * INVR;
        }
        __syncthreads();

        #pragma unroll 1
        for (int ci = 0; ci < CIH; ci++) {
            #pragma unroll
            for (int ky = 0; ky < 3; ky++) {
                const int r = wid * PR + ky;   // tile row for pixel-row A
                const float uthr = fminf(sthr[ci][r], sthr[ci][r + 1]);
                const float a0 = sx[ci][r][tx + 0];
                const float a1 = sx[ci][r][tx + 1];
                const float a2 = sx[ci][r][tx + 2];
                const float b0 = sx[ci][r + 1][tx + 0];
                const float b1 = sx[ci][r + 1][tx + 1];
                const float b2 = sx[ci][r + 1][tx + 2];
                float4 ub = swb[(ci0 + ci) * 3 + ky];
                if (ub.x > uthr) { EKV_TERM(a0, ub.x, accA); EKV_TERM(b0, ub.x, accB); }
                if (ub.y > uthr) { EKV_TERM(a1, ub.y, accA); EKV_TERM(b1, ub.y, accB); }
                if (ub.z > uthr) { EKV_TERM(a2, ub.z, accA); EKV_TERM(b2, ub.z, accB); }
            }
        }
    }
#undef EKV_TERM

    const float sc = scale[0] * (0.05625f * 0.1f);   // ALPHA * R * scale
    const int yA = y0 + wid * PR;
    out[((b * COUTT + co) * HH + yA + 0) * WW + tx] = accA * sc;
    out[((b * COUTT + co) * HH + yA + 1) * WW + tx] = accB * sc;
}

extern "C" void kernel_launch(void* const* d_in, const int* in_sizes, int n_in,
                              void* d_out, int out_size) {
    const float* x     = (const float*)d_in[0];
    const float* theta = (const float*)d_in[1];
    const float* scale = (const float*)d_in[2];
    float* out = (float*)d_out;
    (void)in_sizes; (void)n_in; (void)out_size;

    build_table_kernel<<<3, 256>>>();

    dim3 grid(HH / RPB, COUTT, BB);   // 2 x 64 x 8 = 1024 blocks
    dim3 block(NTHR);
    ekv_conv_kernel<<<grid, block>>>(x, theta, scale, out);
}

// round 11
// speedup vs baseline: 1.3805x; 1.3805x over previous
#include <cuda_runtime.h>

// EKVNonLinearConv: u-space PWL table + per-(cout,ci) descending-sorted term lists.
//   f(d) = sp(min(a,20))^2 - sp(min(a-D,20))^2, a=d/0.075 ; out = ALPHA*R*scale*sum f
//   u = saturate(vg*INVR + ub), ub=(0.96-clip(th,1,8))/2.58 ; idx=floor(u*516)
//   tab entries >=512 exact zero (f==0 for d>=1.6); kinks d=1.5->492, 1.6->512 on-grid.
//   Prep kernel sorts each (cout,ci)'s 9 taps by ub desc; conv warp walks the list and
//   breaks at its per-ci cutoff (max over the warp's 4-row slab, margin 0.55:
//   f(-0.55) ~ 4e-7 -> skipped terms contribute < 1e-6 absolute).

#define CIN    16
#define COUTT  64
#define HH     32
#define WW     32
#define BB     8
#define CG     2
#define NWARP  8
#define PR     2
#define NTHR   256
#define RPB    16             // NWARP*PR output rows per block
#define TILR   18             // +2 halo
#define LPC    144
#define NCG    32             // cout groups

#define TABN   516
#define TABEXT 518
#define TD0    (-0.96f)
#define THD    0.005f
#define INVR   0.3875968992248062f   // 1/2.58
#define USCALE 516.0f
#define CUTC   0.41f                 // 0.96 - 0.55 (skip margin)

__device__ float2 g_tab[TABEXT];            // (a0,a1): f ~= a1*u + a0
__device__ float2 g_list[NCG * CIN * CG * 9]; // {ub, bitcast smem byte-offset}

__device__ __forceinline__ float ekv_exact(float d) {
    const float INVD  = 13.333333333333334f;
    const float DELTA = 1.3333333333333333f;
    float a  = d * INVD;
    float a1 = fminf(fmaxf(a, -50.0f), 20.0f);
    float a2 = fminf(fmaxf(a - DELTA, -50.0f), 20.0f);
    float l1 = log1pf(expf(a1));
    float l2 = log1pf(expf(a2));
    return fmaf(l1, l1, -l2 * l2);
}

__global__ void prep_kernel(const float* __restrict__ theta) {
    int tid = threadIdx.x;
    if (blockIdx.x == NCG) {            // table builder block
        for (int i = tid; i < TABEXT; i += NTHR) {
            float f0 = ekv_exact(TD0 + (float)i * THD);
            float f1 = ekv_exact(TD0 + (float)(i + 1) * THD);
            float a1 = (f1 - f0) * USCALE;
            float u0 = (float)i * (1.0f / USCALE);
            g_tab[i] = make_float2(fmaf(-a1, u0, f0), a1);   // i>=512: exact (0,0)
        }
        return;
    }
    int cg = blockIdx.x;
    if (tid < CIN * CG) {
        int ci = tid >> 1, c = tid & 1;
        float ub[9]; int off[9];
        const float* tp = theta + (cg * CG + c) * LPC + ci * 9;
        #pragma unroll
        for (int e = 0; e < 9; e++) {
            float th = fminf(fmaxf(tp[e], 1.0f), 8.0f);
            ub[e] = (0.96f - th) * INVR;
            int ky = e / 3, kx = e - ky * 3;
            off[e] = (ky * 34 + kx) * 4;     // byte offset within a (row,col) tile slab
        }
        // selection sort, descending ub (deterministic)
        for (int i = 0; i < 8; i++) {
            int m = i;
            for (int j = i + 1; j < 9; j++) if (ub[j] > ub[m]) m = j;
            float tu = ub[i]; ub[i] = ub[m]; ub[m] = tu;
            int   to = off[i]; off[i] = off[m]; off[m] = to;
        }
        float2* dst = g_list + ((cg * CIN + ci) * CG + c) * 9;
        for (int e = 0; e < 9; e++)
            dst[e] = make_float2(ub[e], __int_as_float(off[e]));
    }
}

__global__ __launch_bounds__(NTHR)
void ekv_conv_kernel(const float* __restrict__ x,
                     const float* __restrict__ scale,
                     float* __restrict__ out)
{
    __shared__ float  sx[CIN][TILR][34];   // 38.25 KB halo tile
    __shared__ float2 slist[CIN * CG * 9]; // 2.25 KB sorted lists for this cg
    __shared__ float2 tab[TABEXT];         // 4.05 KB
    __shared__ float  srm[CIN][TILR];      // per-(ci,row) max
    __shared__ float  scut[CIN][NWARP];    // per-(ci,warp) cutoff

    const int rt = blockIdx.x;       // 0..1
    const int cg = blockIdx.y;       // 0..31
    const int b  = blockIdx.z;
    const int y0 = rt * RPB;
    const int tid = threadIdx.x;

    for (int i = tid; i < TABEXT; i += NTHR) tab[i] = g_tab[i];
    {
        const float2* src = g_list + cg * (CIN * CG * 9);
        for (int i = tid; i < CIN * CG * 9; i += NTHR) slist[i] = src[i];
    }
    for (int i = tid; i < CIN * TILR * 34; i += NTHR) {
        int cc = i % 34;
        int r  = (i / 34) % TILR;
        int ci = i / (34 * TILR);
        int gy = y0 - 1 + r;
        int gx = cc - 1;
        float v = 0.0f;
        if (gy >= 0 && gy < HH && gx >= 0 && gx < WW)
            v = x[((b * CIN + ci) * HH + gy) * WW + gx];
        sx[ci][r][cc] = v;
    }
    __syncthreads();
    for (int i = tid; i < CIN * TILR; i += NTHR) {
        int r  = i % TILR;
        int ci = i / TILR;
        float m = -1e30f;
        #pragma unroll
        for (int cc = 0; cc < 34; cc++) m = fmaxf(m, sx[ci][r][cc]);
        srm[ci][r] = m;
    }
    __syncthreads();
    if (tid < CIN * NWARP) {
        int w = tid & 7, ci = tid >> 3;
        float m = fmaxf(fmaxf(srm[ci][2 * w], srm[ci][2 * w + 1]),
                        fmaxf(srm[ci][2 * w + 2], srm[ci][2 * w + 3]));
        scut[ci][w] = (CUTC - m) * INVR;
    }
    __syncthreads();

    const int tx  = tid & 31;
    const int wid = tid >> 5;

    float accA0 = 0.0f, accB0 = 0.0f;   // cout c0,   pixel rows A/B
    float accA1 = 0.0f, accB1 = 0.0f;   // cout c0+1

#define EKV_PIX(VG, UB, ACC) do {                                    \
        float u_ = __saturatef(fmaf((VG), INVR, (UB)));              \
        int i_ = __float2int_rd(u_ * USCALE);                        \
        float2 e_ = tab[i_];                                         \
        (ACC) += fmaf(e_.y, u_, e_.x);                               \
    } while (0)

    #pragma unroll 1
    for (int ci = 0; ci < CIN; ci++) {
        const float cut = scut[ci][wid];
        const char* base = (const char*)&sx[ci][wid * PR][tx];
        const float2* l = &slist[ci * CG * 9];
        #pragma unroll
        for (int e = 0; e < 9; e++) {          // cout c0, sorted desc
            float2 pe = l[e];
            if (pe.x <= cut) break;            // warp-uniform early exit
            const float* p = (const float*)(base + __float_as_int(pe.y));
            float vA = p[0], vB = p[34];
            EKV_PIX(vA, pe.x, accA0);
            EKV_PIX(vB, pe.x, accB0);
        }
        #pragma unroll
        for (int e = 0; e < 9; e++) {          // cout c0+1
            float2 pe = l[9 + e];
            if (pe.x <= cut) break;
            const float* p = (const float*)(base + __float_as_int(pe.y));
            float vA = p[0], vB = p[34];
            EKV_PIX(vA, pe.x, accA1);
            EKV_PIX(vB, pe.x, accB1);
        }
    }
#undef EKV_PIX

    const float sc = scale[0] * (0.05625f * 0.1f);   // ALPHA * R * scale
    const int yA = y0 + wid * PR;
    const int co = cg * CG;
    out[((b * COUTT + co + 0) * HH + yA + 0) * WW + tx] = accA0 * sc;
    out[((b * COUTT + co + 0) * HH + yA + 1) * WW + tx] = accB0 * sc;
    out[((b * COUTT + co + 1) * HH + yA + 0) * WW + tx] = accA1 * sc;
    out[((b * COUTT + co + 1) * HH + yA + 1) * WW + tx] = accB1 * sc;
}

extern "C" void kernel_launch(void* const* d_in, const int* in_sizes, int n_in,
                              void* d_out, int out_size) {
    const float* x     = (const float*)d_in[0];
    const float* theta = (const float*)d_in[1];
    const float* scale = (const float*)d_in[2];
    float* out = (float*)d_out;
    (void)in_sizes; (void)n_in; (void)out_size;

    prep_kernel<<<NCG + 1, NTHR>>>(theta);

    dim3 grid(HH / RPB, NCG, BB);   // 2 x 32 x 8 = 512 blocks
    dim3 block(NTHR);
    ekv_conv_kernel<<<grid, block>>>(x, scale, out);
}